// round 1
// baseline (speedup 1.0000x reference)
#include <cuda_runtime.h>
#include <cstdint>

// WanRotaryPosEmbedS2VStyle: build (freqs_cos, freqs_sin) grids.
//
// Shapes (fixed by the problem instance):
//   hidden_states: (1,16,22,120,120)  -> only H=W=120 matters -> height=width=60
//   t tables: (1024, 44), h/w tables: (1024, 42)
//   output: cos (1, F*3600, 1, 128) followed by sin, F = nvf + nrf (p_t = 1)
//
// Pure gather: out[tok,d] = t_tab[pos_t(f),d] | h_tab[y,d-44] | w_tab[x,d-86]
// HBM-write bound (~81 MB of stores, ~0 read traffic).

#define T_DIM 44
#define H_DIM 42
#define W_DIM 42
#define GRID_W 60
#define GRID_HW 3600   // 60*60 tokens per frame
#define FIXED_REF 30

__global__ void wan_rope_kernel(
    const float* __restrict__ tcos, const float* __restrict__ hcos,
    const float* __restrict__ wcos, const float* __restrict__ tsin,
    const float* __restrict__ hsin, const float* __restrict__ wsin,
    const int*   __restrict__ nvf_p,
    float* __restrict__ out, int n_tok)
{
    const int idx   = blockIdx.x * blockDim.x + threadIdx.x;
    const int total = n_tok * 32;          // 32 float4-groups per token
    if (idx >= total) return;

    const int tok = idx >> 5;              // all 32 lanes of a warp share one token
    const int d0  = (idx & 31) << 2;       // channel group start: 0,4,...,124

    const int f   = tok / GRID_HW;
    const int rem = tok - f * GRID_HW;
    const int y   = rem / GRID_W;
    const int x   = rem - y * GRID_W;

    const int video_pp = __ldg(nvf_p);     // p_t == 1
    const int pt = (f < video_pp) ? f : FIXED_REF;

    float cv[4], sv[4];
#pragma unroll
    for (int k = 0; k < 4; k++) {
        const int d = d0 + k;
        if (d < T_DIM) {
            cv[k] = __ldg(tcos + pt * T_DIM + d);
            sv[k] = __ldg(tsin + pt * T_DIM + d);
        } else if (d < T_DIM + H_DIM) {
            const int dd = d - T_DIM;
            cv[k] = __ldg(hcos + y * H_DIM + dd);
            sv[k] = __ldg(hsin + y * H_DIM + dd);
        } else {
            const int dd = d - (T_DIM + H_DIM);
            cv[k] = __ldg(wcos + x * W_DIM + dd);
            sv[k] = __ldg(wsin + x * W_DIM + dd);
        }
    }

    const float4 c4 = make_float4(cv[0], cv[1], cv[2], cv[3]);
    const float4 s4 = make_float4(sv[0], sv[1], sv[2], sv[3]);

    const size_t base = (size_t)tok * 128 + d0;
    *reinterpret_cast<float4*>(out + base)                          = c4;
    *reinterpret_cast<float4*>(out + (size_t)n_tok * 128 + base)    = s4;
}

extern "C" void kernel_launch(void* const* d_in, const int* in_sizes, int n_in,
                              void* d_out, int out_size)
{
    // metadata order:
    // 0: hidden_states (unused — only its fixed shape matters)
    // 1: freq_t_cos  2: freq_h_cos  3: freq_w_cos
    // 4: freq_t_sin  5: freq_h_sin  6: freq_w_sin
    // 7: num_video_frames (int32)   8: num_ref_frames (int32)
    const float* tcos = (const float*)d_in[1];
    const float* hcos = (const float*)d_in[2];
    const float* wcos = (const float*)d_in[3];
    const float* tsin = (const float*)d_in[4];
    const float* hsin = (const float*)d_in[5];
    const float* wsin = (const float*)d_in[6];
    const int*   nvf  = (const int*)d_in[7];

    float* out = (float*)d_out;

    // out_size = 2 * n_tok * 128
    const int n_tok = out_size / 256;
    const int total = n_tok * 32;
    const int threads = 256;
    const int blocks = (total + threads - 1) / threads;

    wan_rope_kernel<<<blocks, threads>>>(tcos, hcos, wcos, tsin, hsin, wsin,
                                         nvf, out, n_tok);
}

// round 2
// speedup vs baseline: 1.3643x; 1.3643x over previous
#include <cuda_runtime.h>
#include <cstdint>

// WanRotaryPosEmbedS2VStyle: build (freqs_cos, freqs_sin) grids.
//
//   output: cos (1, F*3600, 1, 128) then sin; F*3600 tokens, 128 channels.
//   Per token (f,y,x): channels [0,44)=t_tab[pt], [44,86)=h_tab[y], [86,128)=w_tab[x].
//
// R2: LSU-bound (L1 71.7%, issue 73.4% in R1). Vectorize table gathers as
// float2 (all table row strides are even floats -> every even-d pair is
// 8B-aligned within one table). 4x LDG.64 + 2x STG.128 per 32 output bytes.

#define T_DIM 44
#define H_DIM 42
#define W_DIM 42
#define GRID_W 60
#define GRID_HW 3600
#define FIXED_REF 30

__global__ void wan_rope_kernel(
    const float* __restrict__ tcos, const float* __restrict__ hcos,
    const float* __restrict__ wcos, const float* __restrict__ tsin,
    const float* __restrict__ hsin, const float* __restrict__ wsin,
    const int*   __restrict__ nvf_p,
    float* __restrict__ out, int n_tok, int total)
{
    const int idx = blockIdx.x * blockDim.x + threadIdx.x;
    if (idx >= total) return;

    const int tok = idx >> 5;              // warp lanes share one token
    const int d0  = (idx & 31) << 2;       // channel group: 0,4,...,124

    const int f   = tok / GRID_HW;
    const int rem = tok - f * GRID_HW;
    const int y   = rem / GRID_W;
    const int x   = rem - y * GRID_W;

    const int video_pp = __ldg(nvf_p);
    const int pt = (f < video_pp) ? f : FIXED_REF;

    const int tbase = pt * T_DIM;
    const int hbase = y * H_DIM - T_DIM;            // + d gives h offset
    const int wbase = x * W_DIM - (T_DIM + H_DIM);  // + d gives w offset

    float2 c[2], s[2];
#pragma unroll
    for (int half = 0; half < 2; half++) {
        const int d = d0 + 2 * half;       // even; pair (d, d+1) in one table
        const float* pc;
        const float* ps;
        if (d < T_DIM)              { pc = tcos + tbase + d; ps = tsin + tbase + d; }
        else if (d < T_DIM + H_DIM) { pc = hcos + hbase + d; ps = hsin + hbase + d; }
        else                        { pc = wcos + wbase + d; ps = wsin + wbase + d; }
        c[half] = __ldg(reinterpret_cast<const float2*>(pc));
        s[half] = __ldg(reinterpret_cast<const float2*>(ps));
    }

    const float4 c4 = make_float4(c[0].x, c[0].y, c[1].x, c[1].y);
    const float4 s4 = make_float4(s[0].x, s[0].y, s[1].x, s[1].y);

    const size_t base = (size_t)tok * 128 + d0;
    *reinterpret_cast<float4*>(out + base)                       = c4;
    *reinterpret_cast<float4*>(out + (size_t)n_tok * 128 + base) = s4;
}

extern "C" void kernel_launch(void* const* d_in, const int* in_sizes, int n_in,
                              void* d_out, int out_size)
{
    // 0: hidden_states (unused)
    // 1: freq_t_cos  2: freq_h_cos  3: freq_w_cos
    // 4: freq_t_sin  5: freq_h_sin  6: freq_w_sin
    // 7: num_video_frames (int32)   8: num_ref_frames (int32)
    const float* tcos = (const float*)d_in[1];
    const float* hcos = (const float*)d_in[2];
    const float* wcos = (const float*)d_in[3];
    const float* tsin = (const float*)d_in[4];
    const float* hsin = (const float*)d_in[5];
    const float* wsin = (const float*)d_in[6];
    const int*   nvf  = (const int*)d_in[7];

    float* out = (float*)d_out;

    const int n_tok = out_size / 256;      // out_size = 2 * n_tok * 128
    const int total = n_tok * 32;
    const int threads = 256;
    const int blocks = (total + threads - 1) / threads;

    wan_rope_kernel<<<blocks, threads>>>(tcos, hcos, wcos, tsin, hsin, wsin,
                                         nvf, out, n_tok, total);
}

// round 3
// speedup vs baseline: 1.5496x; 1.1358x over previous
#include <cuda_runtime.h>
#include <cstdint>

// WanRotaryPosEmbedS2VStyle: build (freqs_cos, freqs_sin) grids.
//
//   output: cos (1, n_tok, 1, 128) then sin; n_tok = F*3600 tokens.
//   Per token (f,y,x): ch [0,44)=t_tab[pt], [44,86)=h_tab[y], [86,128)=w_tab[x].
//
// R3: R2 was issue/ALU-bound (~150 warp-instr per 512B token). Each warp now
// handles 4 consecutive x-tokens (same f,y): index math + t/h loads done once,
// per extra token only the w-halves (d>=86) reload (predicated LDG.64,
// pointer += W_DIM) plus 2x STG.128. ~6x fewer instructions per token.

#define T_DIM 44
#define H_DIM 42
#define W_DIM 42
#define GRID_W 60
#define GRID_HW 3600
#define FIXED_REF 30
#define X_PER 4            // tokens per warp (divides 60; 3600 % X_PER == 0)

__global__ void wan_rope_kernel(
    const float* __restrict__ tcos, const float* __restrict__ hcos,
    const float* __restrict__ wcos, const float* __restrict__ tsin,
    const float* __restrict__ hsin, const float* __restrict__ wsin,
    const int*   __restrict__ nvf_p,
    float* __restrict__ out, int n_tok, int n_warps)
{
    const int gtid = blockIdx.x * blockDim.x + threadIdx.x;
    const int w    = gtid >> 5;
    if (w >= n_warps) return;
    const int lane = gtid & 31;
    const int d0   = lane << 2;            // channels [d0, d0+4)

    const int tok0 = w * X_PER;            // X_PER tokens, same (f,y) row
    const int f    = tok0 / GRID_HW;
    const int rem  = tok0 - f * GRID_HW;
    const int y    = rem / GRID_W;

    const int video_pp = __ldg(nvf_p);
    const int pt = (f < video_pp) ? f : FIXED_REF;

    const int tbase = pt * T_DIM;
    const int hbase = y * H_DIM - T_DIM;
    const int wbase = (rem - y * GRID_W) * W_DIM - (T_DIM + H_DIM); // x0 * W_DIM - 86

    const float* pc[2];
    const float* ps[2];
    bool   isw[2];
    float2 c[2], s[2];
#pragma unroll
    for (int h = 0; h < 2; h++) {
        const int d = d0 + 2 * h;          // even; pair (d,d+1) in one table
        if (d < T_DIM)              { pc[h] = tcos + tbase + d; ps[h] = tsin + tbase + d; isw[h] = false; }
        else if (d < T_DIM + H_DIM) { pc[h] = hcos + hbase + d; ps[h] = hsin + hbase + d; isw[h] = false; }
        else                        { pc[h] = wcos + wbase + d; ps[h] = wsin + wbase + d; isw[h] = true;  }
        c[h] = __ldg(reinterpret_cast<const float2*>(pc[h]));
        s[h] = __ldg(reinterpret_cast<const float2*>(ps[h]));
    }

    float* oc = out + (size_t)tok0 * 128 + d0;
    float* os = oc + (size_t)n_tok * 128;

#pragma unroll
    for (int xi = 0; xi < X_PER; xi++) {
        if (xi) {
#pragma unroll
            for (int h = 0; h < 2; h++) {
                if (isw[h]) {              // predicated: only w-lanes reload
                    pc[h] += W_DIM;  ps[h] += W_DIM;
                    c[h] = __ldg(reinterpret_cast<const float2*>(pc[h]));
                    s[h] = __ldg(reinterpret_cast<const float2*>(ps[h]));
                }
            }
        }
        *reinterpret_cast<float4*>(oc) = make_float4(c[0].x, c[0].y, c[1].x, c[1].y);
        *reinterpret_cast<float4*>(os) = make_float4(s[0].x, s[0].y, s[1].x, s[1].y);
        oc += 128;  os += 128;
    }
}

extern "C" void kernel_launch(void* const* d_in, const int* in_sizes, int n_in,
                              void* d_out, int out_size)
{
    // 0: hidden_states (unused)
    // 1: freq_t_cos  2: freq_h_cos  3: freq_w_cos
    // 4: freq_t_sin  5: freq_h_sin  6: freq_w_sin
    // 7: num_video_frames (int32)   8: num_ref_frames (int32)
    const float* tcos = (const float*)d_in[1];
    const float* hcos = (const float*)d_in[2];
    const float* wcos = (const float*)d_in[3];
    const float* tsin = (const float*)d_in[4];
    const float* hsin = (const float*)d_in[5];
    const float* wsin = (const float*)d_in[6];
    const int*   nvf  = (const int*)d_in[7];

    float* out = (float*)d_out;

    const int n_tok   = out_size / 256;    // out_size = 2 * n_tok * 128
    const int n_warps = n_tok / X_PER;     // n_tok = F*3600, divisible by X_PER
    const int threads = 256;
    const int blocks  = (n_warps * 32 + threads - 1) / threads;

    wan_rope_kernel<<<blocks, threads>>>(tcos, hcos, wcos, tsin, hsin, wsin,
                                         nvf, out, n_tok, n_warps);
}